// round 1
// baseline (speedup 1.0000x reference)
#include <cuda_runtime.h>

#define N_NODES 100000
#define N_EDGES 1600000
#define HDIM 128
#define GDIM 64
#define DDIM 64

// ---------------- scratch (device globals; no allocation allowed) ----------
__device__ float g_hs[(size_t)N_NODES * HDIM];    // (x @ W) * dinv[row]
__device__ float g_bufA[(size_t)N_NODES * HDIM];  // x1 / x3
__device__ float g_bufB[(size_t)N_NODES * HDIM];  // x2
__device__ int   g_cnt[N_NODES];
__device__ int   g_tmp[N_NODES];
__device__ int   g_offs[N_NODES + 1];
__device__ int   g_woff[N_NODES];
__device__ int   g_srcs[N_EDGES];
__device__ float g_dinv[N_NODES];
__device__ int   g_bsum[128];
__device__ float g_pool[GDIM * HDIM];
__device__ float g_gcnt[GDIM];

// ---------------- CSR build ------------------------------------------------
__global__ void zero_cnt_kernel() {
    int i = blockIdx.x * blockDim.x + threadIdx.x;
    if (i < N_NODES) g_cnt[i] = 0;
}

__global__ void count_kernel(const int* __restrict__ dst) {
    int e = blockIdx.x * blockDim.x + threadIdx.x;
    if (e < N_EDGES) atomicAdd(&g_cnt[dst[e]], 1);
}

// inclusive per-block scan of g_cnt into g_tmp, block sums into g_bsum
__global__ void scan_part_kernel() {
    __shared__ int s[1024];
    int i = blockIdx.x * 1024 + threadIdx.x;
    int v = (i < N_NODES) ? g_cnt[i] : 0;
    s[threadIdx.x] = v;
    __syncthreads();
#pragma unroll
    for (int off = 1; off < 1024; off <<= 1) {
        int t = 0;
        if (threadIdx.x >= off) t = s[threadIdx.x - off];
        __syncthreads();
        if (threadIdx.x >= off) s[threadIdx.x] += t;
        __syncthreads();
    }
    if (i < N_NODES) g_tmp[i] = s[threadIdx.x];
    if (threadIdx.x == 1023) g_bsum[blockIdx.x] = s[1023];
}

// exclusive scan of block sums (nblocks <= 128), single block of 128 threads
__global__ void scan_bsum_kernel(int nblocks) {
    __shared__ int s[128];
    int v = (threadIdx.x < nblocks) ? g_bsum[threadIdx.x] : 0;
    s[threadIdx.x] = v;
    __syncthreads();
#pragma unroll
    for (int off = 1; off < 128; off <<= 1) {
        int t = 0;
        if (threadIdx.x >= off) t = s[threadIdx.x - off];
        __syncthreads();
        if (threadIdx.x >= off) s[threadIdx.x] += t;
        __syncthreads();
    }
    g_bsum[threadIdx.x] = s[threadIdx.x] - v;  // exclusive
}

__global__ void finalize_offs_kernel() {
    int i = blockIdx.x * blockDim.x + threadIdx.x;
    if (i < N_NODES) {
        int bs = g_bsum[i >> 10];
        int incl = g_tmp[i] + bs;
        int excl = incl - g_cnt[i];
        g_offs[i] = excl;
        g_woff[i] = excl;
        g_dinv[i] = rsqrtf((float)g_cnt[i] + 1.0f);  // +1 self loop
        if (i == N_NODES - 1) g_offs[N_NODES] = incl;
    }
}

__global__ void fill_csr_kernel(const int* __restrict__ src, const int* __restrict__ dst) {
    int e = blockIdx.x * blockDim.x + threadIdx.x;
    if (e < N_EDGES) {
        int d = dst[e];
        int p = atomicAdd(&g_woff[d], 1);
        g_srcs[p] = src[e];
    }
}

// ---------------- GEMM: hs = (A @ W) * dinv[row]  (A: [N,128], W: [128,128])
#define BM 128
#define BN 128
#define BK 32

__global__ __launch_bounds__(256, 2) void gemm_scaled_kernel(
    const float* __restrict__ A, const float* __restrict__ W) {
    __shared__ float As[BM][BK + 4];  // [m][k], +4 pad keeps float4 alignment
    __shared__ float Ws[BK][BN];      // [k][n]

    int t = threadIdx.x;
    int row0 = blockIdx.x * BM;
    int ty = t / 16;  // m-group 0..15
    int tx = t % 16;  // n-group 0..15

    float acc[8][8];
#pragma unroll
    for (int i = 0; i < 8; i++)
#pragma unroll
        for (int j = 0; j < 8; j++) acc[i][j] = 0.f;

    for (int k0 = 0; k0 < HDIM; k0 += BK) {
        // load A tile: 128 rows x 32 cols, coalesced float4
#pragma unroll
        for (int i = 0; i < 4; i++) {
            int ar = (t >> 3) + i * 32;
            int ac = (t & 7) * 4;
            int grow = row0 + ar;
            float4 v = make_float4(0.f, 0.f, 0.f, 0.f);
            if (grow < N_NODES)
                v = *(const float4*)&A[(size_t)grow * HDIM + k0 + ac];
            *(float4*)&As[ar][ac] = v;
        }
        // load W tile: 32 rows x 128 cols
#pragma unroll
        for (int i = 0; i < 4; i++) {
            int wr = (t >> 5) + i * 8;
            int wc = (t & 31) * 4;
            *(float4*)&Ws[wr][wc] = *(const float4*)&W[(size_t)(k0 + wr) * HDIM + wc];
        }
        __syncthreads();

#pragma unroll
        for (int kk = 0; kk < BK; kk++) {
            float a[8], b[8];
#pragma unroll
            for (int i = 0; i < 8; i++) a[i] = As[ty * 8 + i][kk];
            *(float4*)&b[0] = *(float4*)&Ws[kk][tx * 8];
            *(float4*)&b[4] = *(float4*)&Ws[kk][tx * 8 + 4];
#pragma unroll
            for (int i = 0; i < 8; i++)
#pragma unroll
                for (int j = 0; j < 8; j++) acc[i][j] += a[i] * b[j];
        }
        __syncthreads();
    }

#pragma unroll
    for (int i = 0; i < 8; i++) {
        int grow = row0 + ty * 8 + i;
        if (grow < N_NODES) {
            float dv = g_dinv[grow];
#pragma unroll
            for (int j = 0; j < 8; j += 4) {
                float4 v = make_float4(acc[i][j] * dv, acc[i][j + 1] * dv,
                                       acc[i][j + 2] * dv, acc[i][j + 3] * dv);
                *(float4*)&g_hs[(size_t)grow * HDIM + tx * 8 + j] = v;
            }
        }
    }
}

// ---------------- aggregation + bias + BN + LeakyReLU + residual -----------
// agg[i] = dinv[i] * (hs[i] + sum_{e: dst=i} hs[src_e]); hs already has dinv[src]
__global__ __launch_bounds__(256) void agg_post_kernel(
    const float* __restrict__ b, const float* __restrict__ g,
    const float* __restrict__ be, const float* __restrict__ m,
    const float* __restrict__ v, const float* __restrict__ res,
    float* __restrict__ out) {
    int i = blockIdx.x * 2 + (threadIdx.x >> 7);
    int f = threadIdx.x & 127;
    if (i >= N_NODES) return;

    float acc = g_hs[(size_t)i * HDIM + f];
    int e0 = g_offs[i], e1 = g_offs[i + 1];
    int e = e0;
    for (; e + 4 <= e1; e += 4) {
        int s0 = g_srcs[e], s1 = g_srcs[e + 1], s2 = g_srcs[e + 2], s3 = g_srcs[e + 3];
        float a0 = g_hs[(size_t)s0 * HDIM + f];
        float a1 = g_hs[(size_t)s1 * HDIM + f];
        float a2 = g_hs[(size_t)s2 * HDIM + f];
        float a3 = g_hs[(size_t)s3 * HDIM + f];
        acc += (a0 + a1) + (a2 + a3);
    }
    for (; e < e1; e++) acc += g_hs[(size_t)g_srcs[e] * HDIM + f];

    float val = acc * g_dinv[i] + b[f];
    val = (val - m[f]) * rsqrtf(v[f] + 1e-5f) * g[f] + be[f];
    val = (val >= 0.f) ? val : 0.01f * val;
    if (res) val += res[(size_t)i * HDIM + f];
    out[(size_t)i * HDIM + f] = val;
}

// ---------------- pooling ---------------------------------------------------
__global__ void zero_pool_kernel() {
    int i = blockIdx.x * blockDim.x + threadIdx.x;
    if (i < GDIM * HDIM) g_pool[i] = 0.f;
    if (i < GDIM) g_gcnt[i] = 0.f;
}

#define POOL_CHUNK 256
__global__ void pool_sum_kernel(const float* __restrict__ x,
                                const int* __restrict__ batch) {
    int f = threadIdx.x;  // 128
    int n0 = blockIdx.x * POOL_CHUNK;
    int n1 = n0 + POOL_CHUNK;
    if (n1 > N_NODES) n1 = N_NODES;
    if (n0 >= N_NODES) return;

    float acc = 0.f;
    int cur = batch[n0];
    int cnt = 0;
    for (int i = n0; i < n1; i++) {
        int gid = batch[i];
        if (gid != cur) {
            atomicAdd(&g_pool[cur * HDIM + f], acc);
            if (f == 0) atomicAdd(&g_gcnt[cur], (float)cnt);
            acc = 0.f;
            cnt = 0;
            cur = gid;
        }
        acc += x[(size_t)i * HDIM + f];
        cnt++;
    }
    atomicAdd(&g_pool[cur * HDIM + f], acc);
    if (f == 0) atomicAdd(&g_gcnt[cur], (float)cnt);
}

__global__ void pool_mean_kernel() {
    int i = blockIdx.x * blockDim.x + threadIdx.x;
    if (i < GDIM * HDIM) g_pool[i] /= fmaxf(g_gcnt[i / HDIM], 1.0f);
}

// ---------------- MLP head + L2-normalize (single block) -------------------
__global__ __launch_bounds__(256) void head_kernel(
    const float* __restrict__ fcW1, const float* __restrict__ fcb1,
    const float* __restrict__ fcW2, const float* __restrict__ fcb2,
    float* __restrict__ out) {
    __shared__ float Hm[GDIM][HDIM];  // 32 KB
    __shared__ float O[GDIM][DDIM];   // 16 KB
    int t = threadIdx.x;

    for (int idx = t; idx < GDIM * HDIM; idx += 256) {
        int gg = idx / HDIM, n = idx % HDIM;
        float a = fcb1[n];
        const float* pr = &g_pool[gg * HDIM];
#pragma unroll 8
        for (int k = 0; k < HDIM; k++) a += pr[k] * fcW1[k * HDIM + n];
        Hm[gg][n] = (a >= 0.f) ? a : 0.01f * a;
    }
    __syncthreads();

    for (int idx = t; idx < GDIM * DDIM; idx += 256) {
        int gg = idx / DDIM, d = idx % DDIM;
        float a = fcb2[d];
#pragma unroll 8
        for (int k = 0; k < HDIM; k++) a += Hm[gg][k] * fcW2[k * DDIM + d];
        O[gg][d] = a;
    }
    __syncthreads();

    if (t < GDIM) {
        float s = 0.f;
#pragma unroll
        for (int d = 0; d < DDIM; d++) s += O[t][d] * O[t][d];
        float inv = 1.0f / fmaxf(sqrtf(s), 1e-12f);
        for (int d = 0; d < DDIM; d++) out[t * DDIM + d] = O[t][d] * inv;
    }
}

// ---------------- launch -----------------------------------------------------
extern "C" void kernel_launch(void* const* d_in, const int* in_sizes, int n_in,
                              void* d_out, int out_size) {
    const float* x    = (const float*)d_in[0];
    const int*   ei   = (const int*)d_in[1];
    const int*   batch= (const int*)d_in[2];
    const float* W1 = (const float*)d_in[3];
    const float* b1 = (const float*)d_in[4];
    const float* W2 = (const float*)d_in[5];
    const float* b2 = (const float*)d_in[6];
    const float* W3 = (const float*)d_in[7];
    const float* b3 = (const float*)d_in[8];
    const float* g1 = (const float*)d_in[9];
    const float* be1= (const float*)d_in[10];
    const float* m1 = (const float*)d_in[11];
    const float* v1 = (const float*)d_in[12];
    const float* g2 = (const float*)d_in[13];
    const float* be2= (const float*)d_in[14];
    const float* m2 = (const float*)d_in[15];
    const float* v2 = (const float*)d_in[16];
    const float* g3 = (const float*)d_in[17];
    const float* be3= (const float*)d_in[18];
    const float* m3 = (const float*)d_in[19];
    const float* v3 = (const float*)d_in[20];
    const float* fcW1 = (const float*)d_in[21];
    const float* fcb1 = (const float*)d_in[22];
    const float* fcW2 = (const float*)d_in[23];
    const float* fcb2 = (const float*)d_in[24];
    float* out = (float*)d_out;

    const int* srcp = ei;
    const int* dstp = ei + N_EDGES;

    float *bufA, *bufB;
    cudaGetSymbolAddress((void**)&bufA, g_bufA);
    cudaGetSymbolAddress((void**)&bufB, g_bufB);

    const int nscan = (N_NODES + 1023) / 1024;  // 98

    // --- CSR build (once per launch, shared by all 3 layers) ---
    zero_cnt_kernel<<<(N_NODES + 255) / 256, 256>>>();
    count_kernel<<<(N_EDGES + 255) / 256, 256>>>(dstp);
    scan_part_kernel<<<nscan, 1024>>>();
    scan_bsum_kernel<<<1, 128>>>(nscan);
    finalize_offs_kernel<<<(N_NODES + 255) / 256, 256>>>();
    fill_csr_kernel<<<(N_EDGES + 255) / 256, 256>>>(srcp, dstp);

    const int ngemm = (N_NODES + BM - 1) / BM;
    const int nagg  = (N_NODES + 1) / 2;

    // layer 1: x -> bufA
    gemm_scaled_kernel<<<ngemm, 256>>>(x, W1);
    agg_post_kernel<<<nagg, 256>>>(b1, g1, be1, m1, v1, (const float*)0, bufA);
    // layer 2: bufA -> bufB (residual bufA)
    gemm_scaled_kernel<<<ngemm, 256>>>(bufA, W2);
    agg_post_kernel<<<nagg, 256>>>(b2, g2, be2, m2, v2, bufA, bufB);
    // layer 3: bufB -> bufA (residual bufB)
    gemm_scaled_kernel<<<ngemm, 256>>>(bufB, W3);
    agg_post_kernel<<<nagg, 256>>>(b3, g3, be3, m3, v3, bufB, bufA);

    // pooling + head
    zero_pool_kernel<<<(GDIM * HDIM + 255) / 256, 256>>>();
    pool_sum_kernel<<<(N_NODES + POOL_CHUNK - 1) / POOL_CHUNK, 128>>>(bufA, batch);
    pool_mean_kernel<<<(GDIM * HDIM + 255) / 256, 256>>>();
    head_kernel<<<1, 256>>>(fcW1, fcb1, fcW2, fcb2, out);
}

// round 2
// speedup vs baseline: 1.4201x; 1.4201x over previous
#include <cuda_runtime.h>
#include <mma.h>

using namespace nvcuda;

#define N_NODES 100000
#define N_EDGES 1600000
#define HDIM 128
#define GDIM 64
#define DDIM 64

// ---------------- scratch (device globals; no allocation allowed) ----------
__device__ float g_hs[(size_t)N_NODES * HDIM];    // (x @ W) * dinv[row]
__device__ float g_bufA[(size_t)N_NODES * HDIM];  // x1 / x3
__device__ float g_bufB[(size_t)N_NODES * HDIM];  // x2
__device__ int   g_cnt[N_NODES];
__device__ int   g_tmp[N_NODES];
__device__ int   g_offs[N_NODES + 1];
__device__ int   g_woff[N_NODES];
__device__ int   g_srcs[N_EDGES];
__device__ float g_dinv[N_NODES];
__device__ int   g_bsum[128];
__device__ float g_pool[GDIM * HDIM];
__device__ float g_gcnt[GDIM];

// ---------------- CSR build ------------------------------------------------
__global__ void zero_cnt_kernel() {
    int i = blockIdx.x * blockDim.x + threadIdx.x;
    if (i < N_NODES) g_cnt[i] = 0;
}

__global__ void count_kernel(const int* __restrict__ dst) {
    int e = blockIdx.x * blockDim.x + threadIdx.x;
    if (e < N_EDGES) atomicAdd(&g_cnt[dst[e]], 1);
}

// inclusive per-block scan of g_cnt into g_tmp, block sums into g_bsum
__global__ void scan_part_kernel() {
    __shared__ int s[1024];
    int i = blockIdx.x * 1024 + threadIdx.x;
    int v = (i < N_NODES) ? g_cnt[i] : 0;
    s[threadIdx.x] = v;
    __syncthreads();
#pragma unroll
    for (int off = 1; off < 1024; off <<= 1) {
        int t = 0;
        if (threadIdx.x >= off) t = s[threadIdx.x - off];
        __syncthreads();
        if (threadIdx.x >= off) s[threadIdx.x] += t;
        __syncthreads();
    }
    if (i < N_NODES) g_tmp[i] = s[threadIdx.x];
    if (threadIdx.x == 1023) g_bsum[blockIdx.x] = s[1023];
}

// exclusive scan of block sums (nblocks <= 128), single block of 128 threads
__global__ void scan_bsum_kernel(int nblocks) {
    __shared__ int s[128];
    int v = (threadIdx.x < nblocks) ? g_bsum[threadIdx.x] : 0;
    s[threadIdx.x] = v;
    __syncthreads();
#pragma unroll
    for (int off = 1; off < 128; off <<= 1) {
        int t = 0;
        if (threadIdx.x >= off) t = s[threadIdx.x - off];
        __syncthreads();
        if (threadIdx.x >= off) s[threadIdx.x] += t;
        __syncthreads();
    }
    g_bsum[threadIdx.x] = s[threadIdx.x] - v;  // exclusive
}

__global__ void finalize_offs_kernel() {
    int i = blockIdx.x * blockDim.x + threadIdx.x;
    if (i < N_NODES) {
        int bs = g_bsum[i >> 10];
        int incl = g_tmp[i] + bs;
        int excl = incl - g_cnt[i];
        g_offs[i] = excl;
        g_woff[i] = excl;
        g_dinv[i] = rsqrtf((float)g_cnt[i] + 1.0f);  // +1 self loop
        if (i == N_NODES - 1) g_offs[N_NODES] = incl;
    }
}

__global__ void fill_csr_kernel(const int* __restrict__ src, const int* __restrict__ dst) {
    int e = blockIdx.x * blockDim.x + threadIdx.x;
    if (e < N_EDGES) {
        int d = dst[e];
        int p = atomicAdd(&g_woff[d], 1);
        g_srcs[p] = src[e];
    }
}

// ---------------- GEMM (TF32 tensor cores): hs = (A @ W) * dinv[row] -------
// A: [N, 128] row-major, W: [128, 128] row-major.
// Block tile 128x128, 8 warps, warp tile 32x64 (2x4 wmma m16n16k8 tiles).
#define GBK 32

__global__ __launch_bounds__(256) void gemm_tf32_kernel(
    const float* __restrict__ A, const float* __restrict__ W) {
    __shared__ float As[128][GBK + 4];   // 18432 B
    __shared__ float Ws[GBK][128 + 4];   // 16896 B
    __shared__ float Cs[8][16][20];      // 10240 B epilogue staging

    int t = threadIdx.x;
    int warp = t >> 5;
    int lane = t & 31;
    int row0 = blockIdx.x * 128;
    int wm = warp >> 1;   // 0..3 -> rows wm*32
    int wn = warp & 1;    // 0..1 -> cols wn*64

    wmma::fragment<wmma::accumulator, 16, 16, 8, float> acc[2][4];
#pragma unroll
    for (int i = 0; i < 2; i++)
#pragma unroll
        for (int j = 0; j < 4; j++) wmma::fill_fragment(acc[i][j], 0.0f);

    for (int k0 = 0; k0 < HDIM; k0 += GBK) {
        // load A tile: 128 x 32 (1024 float4, 256 threads x 4)
#pragma unroll
        for (int i = 0; i < 4; i++) {
            int f4 = t + i * 256;
            int r = f4 >> 3;
            int c = (f4 & 7) * 4;
            int grow = row0 + r;
            float4 v = make_float4(0.f, 0.f, 0.f, 0.f);
            if (grow < N_NODES)
                v = *(const float4*)&A[(size_t)grow * HDIM + k0 + c];
            *(float4*)&As[r][c] = v;
        }
        // load W tile: 32 x 128
#pragma unroll
        for (int i = 0; i < 4; i++) {
            int f4 = t + i * 256;
            int r = f4 >> 5;
            int c = (f4 & 31) * 4;
            *(float4*)&Ws[r][c] = *(const float4*)&W[(size_t)(k0 + r) * HDIM + c];
        }
        __syncthreads();

#pragma unroll
        for (int kk = 0; kk < GBK; kk += 8) {
            wmma::fragment<wmma::matrix_a, 16, 16, 8, wmma::precision::tf32,
                           wmma::row_major> af[2];
#pragma unroll
            for (int i = 0; i < 2; i++) {
                wmma::load_matrix_sync(af[i], &As[wm * 32 + i * 16][kk], GBK + 4);
#pragma unroll
                for (int e = 0; e < af[i].num_elements; e++)
                    af[i].x[e] = wmma::__float_to_tf32(af[i].x[e]);
            }
            wmma::fragment<wmma::matrix_b, 16, 16, 8, wmma::precision::tf32,
                           wmma::row_major> bf[4];
#pragma unroll
            for (int j = 0; j < 4; j++) {
                wmma::load_matrix_sync(bf[j], &Ws[kk][wn * 64 + j * 16], 128 + 4);
#pragma unroll
                for (int e = 0; e < bf[j].num_elements; e++)
                    bf[j].x[e] = wmma::__float_to_tf32(bf[j].x[e]);
            }
#pragma unroll
            for (int i = 0; i < 2; i++)
#pragma unroll
                for (int j = 0; j < 4; j++)
                    wmma::mma_sync(acc[i][j], af[i], bf[j], acc[i][j]);
        }
        __syncthreads();
    }

    // epilogue: stage 16x16 tiles through smem, scale by dinv[row], store
#pragma unroll
    for (int i = 0; i < 2; i++) {
#pragma unroll
        for (int j = 0; j < 4; j++) {
            wmma::store_matrix_sync(&Cs[warp][0][0], acc[i][j], 20,
                                    wmma::mem_row_major);
            __syncwarp();
#pragma unroll
            for (int it = 0; it < 2; it++) {
                int f4 = lane + it * 32;     // 0..63
                int r = f4 >> 2;             // 0..15
                int c4 = f4 & 3;             // 0..3
                int grow = row0 + wm * 32 + i * 16 + r;
                if (grow < N_NODES) {
                    float dv = g_dinv[grow];
                    float4 v = *(float4*)&Cs[warp][r][c4 * 4];
                    v.x *= dv; v.y *= dv; v.z *= dv; v.w *= dv;
                    *(float4*)&g_hs[(size_t)grow * HDIM + wn * 64 + j * 16 + c4 * 4] = v;
                }
            }
            __syncwarp();
        }
    }
}

// ---------------- aggregation + bias + BN + LeakyReLU + residual -----------
// One warp per node; each lane handles 4 consecutive features (float4).
// agg[i] = dinv[i] * (hs[i] + sum_{e: dst=i} hs[src_e]); hs already has dinv[src]
__global__ __launch_bounds__(256) void agg_post_kernel(
    const float* __restrict__ b, const float* __restrict__ g,
    const float* __restrict__ be, const float* __restrict__ m,
    const float* __restrict__ v, const float* __restrict__ res,
    float* __restrict__ out) {
    int node = blockIdx.x * 8 + (threadIdx.x >> 5);
    int lane = threadIdx.x & 31;
    if (node >= N_NODES) return;

    const float4* hs4 = (const float4*)g_hs;
    float4 a0 = hs4[(size_t)node * 32 + lane];
    float sx = a0.x, sy = a0.y, sz = a0.z, sw = a0.w;

    int e0 = g_offs[node], e1 = g_offs[node + 1];
    int e = e0;
    for (; e + 4 <= e1; e += 4) {
        int s0 = g_srcs[e], s1 = g_srcs[e + 1], s2 = g_srcs[e + 2], s3 = g_srcs[e + 3];
        float4 v0 = hs4[(size_t)s0 * 32 + lane];
        float4 v1 = hs4[(size_t)s1 * 32 + lane];
        float4 v2 = hs4[(size_t)s2 * 32 + lane];
        float4 v3 = hs4[(size_t)s3 * 32 + lane];
        sx += (v0.x + v1.x) + (v2.x + v3.x);
        sy += (v0.y + v1.y) + (v2.y + v3.y);
        sz += (v0.z + v1.z) + (v2.z + v3.z);
        sw += (v0.w + v1.w) + (v2.w + v3.w);
    }
    for (; e < e1; e++) {
        float4 v0 = hs4[(size_t)g_srcs[e] * 32 + lane];
        sx += v0.x; sy += v0.y; sz += v0.z; sw += v0.w;
    }

    int c = lane * 4;
    float dv = g_dinv[node];
    float4 bb = *(const float4*)&b[c];
    float4 gg = *(const float4*)&g[c];
    float4 bee = *(const float4*)&be[c];
    float4 mm = *(const float4*)&m[c];
    float4 vv = *(const float4*)&v[c];

    float4 r4;
    r4.x = (sx * dv + bb.x - mm.x) * rsqrtf(vv.x + 1e-5f) * gg.x + bee.x;
    r4.y = (sy * dv + bb.y - mm.y) * rsqrtf(vv.y + 1e-5f) * gg.y + bee.y;
    r4.z = (sz * dv + bb.z - mm.z) * rsqrtf(vv.z + 1e-5f) * gg.z + bee.z;
    r4.w = (sw * dv + bb.w - mm.w) * rsqrtf(vv.w + 1e-5f) * gg.w + bee.w;
    r4.x = (r4.x >= 0.f) ? r4.x : 0.01f * r4.x;
    r4.y = (r4.y >= 0.f) ? r4.y : 0.01f * r4.y;
    r4.z = (r4.z >= 0.f) ? r4.z : 0.01f * r4.z;
    r4.w = (r4.w >= 0.f) ? r4.w : 0.01f * r4.w;

    if (res) {
        float4 rr = *(const float4*)&res[(size_t)node * HDIM + c];
        r4.x += rr.x; r4.y += rr.y; r4.z += rr.z; r4.w += rr.w;
    }
    *(float4*)&out[(size_t)node * HDIM + c] = r4;
}

// ---------------- pooling ---------------------------------------------------
__global__ void zero_pool_kernel() {
    int i = blockIdx.x * blockDim.x + threadIdx.x;
    if (i < GDIM * HDIM) g_pool[i] = 0.f;
    if (i < GDIM) g_gcnt[i] = 0.f;
}

#define POOL_CHUNK 256
__global__ void pool_sum_kernel(const float* __restrict__ x,
                                const int* __restrict__ batch) {
    int f = threadIdx.x;  // 128
    int n0 = blockIdx.x * POOL_CHUNK;
    int n1 = n0 + POOL_CHUNK;
    if (n1 > N_NODES) n1 = N_NODES;
    if (n0 >= N_NODES) return;

    float acc = 0.f;
    int cur = batch[n0];
    int cnt = 0;
    for (int i = n0; i < n1; i++) {
        int gid = batch[i];
        if (gid != cur) {
            atomicAdd(&g_pool[cur * HDIM + f], acc);
            if (f == 0) atomicAdd(&g_gcnt[cur], (float)cnt);
            acc = 0.f;
            cnt = 0;
            cur = gid;
        }
        acc += x[(size_t)i * HDIM + f];
        cnt++;
    }
    atomicAdd(&g_pool[cur * HDIM + f], acc);
    if (f == 0) atomicAdd(&g_gcnt[cur], (float)cnt);
}

__global__ void pool_mean_kernel() {
    int i = blockIdx.x * blockDim.x + threadIdx.x;
    if (i < GDIM * HDIM) g_pool[i] /= fmaxf(g_gcnt[i / HDIM], 1.0f);
}

// ---------------- MLP head + L2-normalize (single block) -------------------
__global__ __launch_bounds__(256) void head_kernel(
    const float* __restrict__ fcW1, const float* __restrict__ fcb1,
    const float* __restrict__ fcW2, const float* __restrict__ fcb2,
    float* __restrict__ out) {
    __shared__ float Hm[GDIM][HDIM];  // 32 KB
    __shared__ float O[GDIM][DDIM];   // 16 KB
    int t = threadIdx.x;

    for (int idx = t; idx < GDIM * HDIM; idx += 256) {
        int gg = idx / HDIM, n = idx % HDIM;
        float a = fcb1[n];
        const float* pr = &g_pool[gg * HDIM];
#pragma unroll 8
        for (int k = 0; k < HDIM; k++) a += pr[k] * fcW1[k * HDIM + n];
        Hm[gg][n] = (a >= 0.f) ? a : 0.01f * a;
    }
    __syncthreads();

    for (int idx = t; idx < GDIM * DDIM; idx += 256) {
        int gg = idx / DDIM, d = idx % DDIM;
        float a = fcb2[d];
#pragma unroll 8
        for (int k = 0; k < HDIM; k++) a += Hm[gg][k] * fcW2[k * DDIM + d];
        O[gg][d] = a;
    }
    __syncthreads();

    if (t < GDIM) {
        float s = 0.f;
#pragma unroll
        for (int d = 0; d < DDIM; d++) s += O[t][d] * O[t][d];
        float inv = 1.0f / fmaxf(sqrtf(s), 1e-12f);
        for (int d = 0; d < DDIM; d++) out[t * DDIM + d] = O[t][d] * inv;
    }
}

// ---------------- launch -----------------------------------------------------
extern "C" void kernel_launch(void* const* d_in, const int* in_sizes, int n_in,
                              void* d_out, int out_size) {
    const float* x    = (const float*)d_in[0];
    const int*   ei   = (const int*)d_in[1];
    const int*   batch= (const int*)d_in[2];
    const float* W1 = (const float*)d_in[3];
    const float* b1 = (const float*)d_in[4];
    const float* W2 = (const float*)d_in[5];
    const float* b2 = (const float*)d_in[6];
    const float* W3 = (const float*)d_in[7];
    const float* b3 = (const float*)d_in[8];
    const float* g1 = (const float*)d_in[9];
    const float* be1= (const float*)d_in[10];
    const float* m1 = (const float*)d_in[11];
    const float* v1 = (const float*)d_in[12];
    const float* g2 = (const float*)d_in[13];
    const float* be2= (const float*)d_in[14];
    const float* m2 = (const float*)d_in[15];
    const float* v2 = (const float*)d_in[16];
    const float* g3 = (const float*)d_in[17];
    const float* be3= (const float*)d_in[18];
    const float* m3 = (const float*)d_in[19];
    const float* v3 = (const float*)d_in[20];
    const float* fcW1 = (const float*)d_in[21];
    const float* fcb1 = (const float*)d_in[22];
    const float* fcW2 = (const float*)d_in[23];
    const float* fcb2 = (const float*)d_in[24];
    float* out = (float*)d_out;

    const int* srcp = ei;
    const int* dstp = ei + N_EDGES;

    float *bufA, *bufB;
    cudaGetSymbolAddress((void**)&bufA, g_bufA);
    cudaGetSymbolAddress((void**)&bufB, g_bufB);

    const int nscan = (N_NODES + 1023) / 1024;  // 98

    // --- CSR build (once per launch, shared by all 3 layers) ---
    zero_cnt_kernel<<<(N_NODES + 255) / 256, 256>>>();
    count_kernel<<<(N_EDGES + 255) / 256, 256>>>(dstp);
    scan_part_kernel<<<nscan, 1024>>>();
    scan_bsum_kernel<<<1, 128>>>(nscan);
    finalize_offs_kernel<<<(N_NODES + 255) / 256, 256>>>();
    fill_csr_kernel<<<(N_EDGES + 255) / 256, 256>>>(srcp, dstp);

    const int ngemm = (N_NODES + 127) / 128;
    const int nagg  = (N_NODES + 7) / 8;

    // layer 1: x -> bufA
    gemm_tf32_kernel<<<ngemm, 256>>>(x, W1);
    agg_post_kernel<<<nagg, 256>>>(b1, g1, be1, m1, v1, (const float*)0, bufA);
    // layer 2: bufA -> bufB (residual bufA)
    gemm_tf32_kernel<<<ngemm, 256>>>(bufA, W2);
    agg_post_kernel<<<nagg, 256>>>(b2, g2, be2, m2, v2, bufA, bufB);
    // layer 3: bufB -> bufA (residual bufB)
    gemm_tf32_kernel<<<ngemm, 256>>>(bufB, W3);
    agg_post_kernel<<<nagg, 256>>>(b3, g3, be3, m3, v3, bufB, bufA);

    // pooling + head
    zero_pool_kernel<<<(GDIM * HDIM + 255) / 256, 256>>>();
    pool_sum_kernel<<<(N_NODES + POOL_CHUNK - 1) / POOL_CHUNK, 128>>>(bufA, batch);
    pool_mean_kernel<<<(GDIM * HDIM + 255) / 256, 256>>>();
    head_kernel<<<1, 256>>>(fcW1, fcb1, fcW2, fcb2, out);
}

// round 3
// speedup vs baseline: 1.8310x; 1.2893x over previous
#include <cuda_runtime.h>
#include <cuda_fp16.h>
#include <mma.h>

using namespace nvcuda;

#define N_NODES 100000
#define N_EDGES 1600000
#define HDIM 128
#define GDIM 64
#define DDIM 64

// ---------------- scratch (device globals; no allocation allowed) ----------
__device__ __half g_hs[(size_t)N_NODES * HDIM];   // fp16 (x @ W) * dinv[row]
__device__ float g_bufA[(size_t)N_NODES * HDIM];  // x1 / x3
__device__ float g_bufB[(size_t)N_NODES * HDIM];  // x2
__device__ int   g_cnt[N_NODES];
__device__ int   g_tmp[N_NODES];
__device__ int   g_offs[N_NODES + 1];
__device__ int   g_woff[N_NODES];
__device__ int   g_srcs[N_EDGES];
__device__ float g_dinv[N_NODES];
__device__ int   g_bsum[128];
__device__ float g_pool[GDIM * HDIM];
__device__ float g_gcnt[GDIM];

// ---------------- CSR build ------------------------------------------------
__global__ void count_kernel(const int* __restrict__ dst) {
    int e = blockIdx.x * blockDim.x + threadIdx.x;
    if (e < N_EDGES) atomicAdd(&g_cnt[dst[e]], 1);
}

// inclusive per-block scan of g_cnt into g_tmp, block sums into g_bsum
__global__ void scan_part_kernel() {
    __shared__ int s[1024];
    int i = blockIdx.x * 1024 + threadIdx.x;
    int v = (i < N_NODES) ? g_cnt[i] : 0;
    s[threadIdx.x] = v;
    __syncthreads();
#pragma unroll
    for (int off = 1; off < 1024; off <<= 1) {
        int t = 0;
        if (threadIdx.x >= off) t = s[threadIdx.x - off];
        __syncthreads();
        if (threadIdx.x >= off) s[threadIdx.x] += t;
        __syncthreads();
    }
    if (i < N_NODES) g_tmp[i] = s[threadIdx.x];
    if (threadIdx.x == 1023) g_bsum[blockIdx.x] = s[1023];
}

// exclusive scan of block sums (nblocks <= 128), single block of 128 threads
__global__ void scan_bsum_kernel(int nblocks) {
    __shared__ int s[128];
    int v = (threadIdx.x < nblocks) ? g_bsum[threadIdx.x] : 0;
    s[threadIdx.x] = v;
    __syncthreads();
#pragma unroll
    for (int off = 1; off < 128; off <<= 1) {
        int t = 0;
        if (threadIdx.x >= off) t = s[threadIdx.x - off];
        __syncthreads();
        if (threadIdx.x >= off) s[threadIdx.x] += t;
        __syncthreads();
    }
    g_bsum[threadIdx.x] = s[threadIdx.x] - v;  // exclusive
}

__global__ void finalize_offs_kernel() {
    int i = blockIdx.x * blockDim.x + threadIdx.x;
    if (i < N_NODES) {
        int bs = g_bsum[i >> 10];
        int incl = g_tmp[i] + bs;
        int excl = incl - g_cnt[i];
        g_offs[i] = excl;
        g_woff[i] = excl;
        g_dinv[i] = rsqrtf((float)g_cnt[i] + 1.0f);  // +1 self loop
        if (i == N_NODES - 1) g_offs[N_NODES] = incl;
    }
}

__global__ void fill_csr_kernel(const int* __restrict__ src, const int* __restrict__ dst) {
    int e = blockIdx.x * blockDim.x + threadIdx.x;
    if (e < N_EDGES) {
        int d = dst[e];
        int p = atomicAdd(&g_woff[d], 1);
        g_srcs[p] = src[e];
    }
}

// ---------------- GEMM (TF32 tensor cores): hs = fp16((A @ W) * dinv[row]) -
// A: [N, 128] row-major fp32, W: [128, 128] row-major fp32.
// Block tile 128x128, 8 warps, warp tile 32x64 (2x4 wmma m16n16k8 tiles).
#define GBK 32

__global__ __launch_bounds__(256) void gemm_tf32_kernel(
    const float* __restrict__ A, const float* __restrict__ W) {
    __shared__ float As[128][GBK + 4];   // values pre-rounded to tf32
    __shared__ float Ws[GBK][128 + 4];
    __shared__ float Cs[8][16][20];      // epilogue staging

    int t = threadIdx.x;
    int warp = t >> 5;
    int lane = t & 31;
    int row0 = blockIdx.x * 128;
    int wm = warp >> 1;   // 0..3 -> rows wm*32
    int wn = warp & 1;    // 0..1 -> cols wn*64

    wmma::fragment<wmma::accumulator, 16, 16, 8, float> acc[2][4];
#pragma unroll
    for (int i = 0; i < 2; i++)
#pragma unroll
        for (int j = 0; j < 4; j++) wmma::fill_fragment(acc[i][j], 0.0f);

    for (int k0 = 0; k0 < HDIM; k0 += GBK) {
        // load A tile: 128 x 32, round to tf32 at store
#pragma unroll
        for (int i = 0; i < 4; i++) {
            int f4 = t + i * 256;
            int r = f4 >> 3;
            int c = (f4 & 7) * 4;
            int grow = row0 + r;
            float4 v = make_float4(0.f, 0.f, 0.f, 0.f);
            if (grow < N_NODES)
                v = *(const float4*)&A[(size_t)grow * HDIM + k0 + c];
            v.x = wmma::__float_to_tf32(v.x);
            v.y = wmma::__float_to_tf32(v.y);
            v.z = wmma::__float_to_tf32(v.z);
            v.w = wmma::__float_to_tf32(v.w);
            *(float4*)&As[r][c] = v;
        }
        // load W tile: 32 x 128, round to tf32 at store
#pragma unroll
        for (int i = 0; i < 4; i++) {
            int f4 = t + i * 256;
            int r = f4 >> 5;
            int c = (f4 & 31) * 4;
            float4 v = *(const float4*)&W[(size_t)(k0 + r) * HDIM + c];
            v.x = wmma::__float_to_tf32(v.x);
            v.y = wmma::__float_to_tf32(v.y);
            v.z = wmma::__float_to_tf32(v.z);
            v.w = wmma::__float_to_tf32(v.w);
            *(float4*)&Ws[r][c] = v;
        }
        __syncthreads();

#pragma unroll
        for (int kk = 0; kk < GBK; kk += 8) {
            wmma::fragment<wmma::matrix_a, 16, 16, 8, wmma::precision::tf32,
                           wmma::row_major> af[2];
#pragma unroll
            for (int i = 0; i < 2; i++)
                wmma::load_matrix_sync(af[i], &As[wm * 32 + i * 16][kk], GBK + 4);
            wmma::fragment<wmma::matrix_b, 16, 16, 8, wmma::precision::tf32,
                           wmma::row_major> bf[4];
#pragma unroll
            for (int j = 0; j < 4; j++)
                wmma::load_matrix_sync(bf[j], &Ws[kk][wn * 64 + j * 16], 128 + 4);
#pragma unroll
            for (int i = 0; i < 2; i++)
#pragma unroll
                for (int j = 0; j < 4; j++)
                    wmma::mma_sync(acc[i][j], af[i], bf[j], acc[i][j]);
        }
        __syncthreads();
    }

    // epilogue: stage 16x16 tiles through smem, scale by dinv[row], fp16 store
#pragma unroll
    for (int i = 0; i < 2; i++) {
#pragma unroll
        for (int j = 0; j < 4; j++) {
            wmma::store_matrix_sync(&Cs[warp][0][0], acc[i][j], 20,
                                    wmma::mem_row_major);
            __syncwarp();
#pragma unroll
            for (int it = 0; it < 2; it++) {
                int f4 = lane + it * 32;     // 0..63
                int r = f4 >> 2;             // 0..15
                int c4 = f4 & 3;             // 0..3
                int grow = row0 + wm * 32 + i * 16 + r;
                if (grow < N_NODES) {
                    float dv = g_dinv[grow];
                    float4 v = *(float4*)&Cs[warp][r][c4 * 4];
                    __half2 h0 = __floats2half2_rn(v.x * dv, v.y * dv);
                    __half2 h1 = __floats2half2_rn(v.z * dv, v.w * dv);
                    uint2 u;
                    u.x = *(const unsigned*)&h0;
                    u.y = *(const unsigned*)&h1;
                    *(uint2*)&g_hs[(size_t)grow * HDIM + wn * 64 + j * 16 + c4 * 4] = u;
                }
            }
            __syncwarp();
        }
    }
}

// ---------------- aggregation + bias + BN + LeakyReLU + residual -----------
// One warp per node; lane handles 4 features (uint2 = 4 halves). fp32 accum.
__global__ __launch_bounds__(256) void agg_post_kernel(
    const float* __restrict__ b, const float* __restrict__ g,
    const float* __restrict__ be, const float* __restrict__ m,
    const float* __restrict__ v, const float* __restrict__ res,
    float* __restrict__ out) {
    int node = blockIdx.x * 8 + (threadIdx.x >> 5);
    int lane = threadIdx.x & 31;
    if (node >= N_NODES) return;

    const uint2* hsu = (const uint2*)g_hs;  // row stride = 32 uint2

    uint2 u0 = hsu[(size_t)node * 32 + lane];
    float2 f0 = __half22float2(*(const __half2*)&u0.x);
    float2 f1 = __half22float2(*(const __half2*)&u0.y);
    float sx = f0.x, sy = f0.y, sz = f1.x, sw = f1.y;

    int e0 = g_offs[node], e1 = g_offs[node + 1];
    int e = e0;
    for (; e + 4 <= e1; e += 4) {
        int s0 = g_srcs[e], s1 = g_srcs[e + 1], s2 = g_srcs[e + 2], s3 = g_srcs[e + 3];
        uint2 a0 = hsu[(size_t)s0 * 32 + lane];
        uint2 a1 = hsu[(size_t)s1 * 32 + lane];
        uint2 a2 = hsu[(size_t)s2 * 32 + lane];
        uint2 a3 = hsu[(size_t)s3 * 32 + lane];
        float2 p;
        p = __half22float2(*(const __half2*)&a0.x); sx += p.x; sy += p.y;
        p = __half22float2(*(const __half2*)&a0.y); sz += p.x; sw += p.y;
        p = __half22float2(*(const __half2*)&a1.x); sx += p.x; sy += p.y;
        p = __half22float2(*(const __half2*)&a1.y); sz += p.x; sw += p.y;
        p = __half22float2(*(const __half2*)&a2.x); sx += p.x; sy += p.y;
        p = __half22float2(*(const __half2*)&a2.y); sz += p.x; sw += p.y;
        p = __half22float2(*(const __half2*)&a3.x); sx += p.x; sy += p.y;
        p = __half22float2(*(const __half2*)&a3.y); sz += p.x; sw += p.y;
    }
    for (; e < e1; e++) {
        uint2 a0 = hsu[(size_t)g_srcs[e] * 32 + lane];
        float2 p;
        p = __half22float2(*(const __half2*)&a0.x); sx += p.x; sy += p.y;
        p = __half22float2(*(const __half2*)&a0.y); sz += p.x; sw += p.y;
    }

    int c = lane * 4;
    float dv = g_dinv[node];
    float4 bb = *(const float4*)&b[c];
    float4 gg = *(const float4*)&g[c];
    float4 bee = *(const float4*)&be[c];
    float4 mm = *(const float4*)&m[c];
    float4 vv = *(const float4*)&v[c];

    float4 r4;
    r4.x = (sx * dv + bb.x - mm.x) * rsqrtf(vv.x + 1e-5f) * gg.x + bee.x;
    r4.y = (sy * dv + bb.y - mm.y) * rsqrtf(vv.y + 1e-5f) * gg.y + bee.y;
    r4.z = (sz * dv + bb.z - mm.z) * rsqrtf(vv.z + 1e-5f) * gg.z + bee.z;
    r4.w = (sw * dv + bb.w - mm.w) * rsqrtf(vv.w + 1e-5f) * gg.w + bee.w;
    r4.x = (r4.x >= 0.f) ? r4.x : 0.01f * r4.x;
    r4.y = (r4.y >= 0.f) ? r4.y : 0.01f * r4.y;
    r4.z = (r4.z >= 0.f) ? r4.z : 0.01f * r4.z;
    r4.w = (r4.w >= 0.f) ? r4.w : 0.01f * r4.w;

    if (res) {
        float4 rr = *(const float4*)&res[(size_t)node * HDIM + c];
        r4.x += rr.x; r4.y += rr.y; r4.z += rr.z; r4.w += rr.w;
    }
    *(float4*)&out[(size_t)node * HDIM + c] = r4;
}

// ---------------- pooling ---------------------------------------------------
#define POOL_CHUNK 256
__global__ void pool_sum_kernel(const float* __restrict__ x,
                                const int* __restrict__ batch) {
    int f = threadIdx.x;  // 128
    int n0 = blockIdx.x * POOL_CHUNK;
    int n1 = n0 + POOL_CHUNK;
    if (n1 > N_NODES) n1 = N_NODES;
    if (n0 >= N_NODES) return;

    float acc = 0.f;
    int cur = batch[n0];
    int cnt = 0;
    for (int i = n0; i < n1; i++) {
        int gid = batch[i];
        if (gid != cur) {
            atomicAdd(&g_pool[cur * HDIM + f], acc);
            if (f == 0) atomicAdd(&g_gcnt[cur], (float)cnt);
            acc = 0.f;
            cnt = 0;
            cur = gid;
        }
        acc += x[(size_t)i * HDIM + f];
        cnt++;
    }
    atomicAdd(&g_pool[cur * HDIM + f], acc);
    if (f == 0) atomicAdd(&g_gcnt[cur], (float)cnt);
}

// ---------------- MLP head + mean + L2-normalize (single block) ------------
__global__ __launch_bounds__(256) void head_kernel(
    const float* __restrict__ fcW1, const float* __restrict__ fcb1,
    const float* __restrict__ fcW2, const float* __restrict__ fcb2,
    float* __restrict__ out) {
    __shared__ float P[GDIM][HDIM];   // mean-pooled
    __shared__ float Hm[GDIM][HDIM];
    __shared__ float O[GDIM][DDIM];
    __shared__ float invc[GDIM];
    int t = threadIdx.x;

    if (t < GDIM) invc[t] = 1.0f / fmaxf(g_gcnt[t], 1.0f);
    __syncthreads();
    for (int idx = t; idx < GDIM * HDIM; idx += 256)
        P[idx / HDIM][idx % HDIM] = g_pool[idx] * invc[idx / HDIM];
    __syncthreads();

    for (int idx = t; idx < GDIM * HDIM; idx += 256) {
        int gg = idx / HDIM, n = idx % HDIM;
        float a = fcb1[n];
#pragma unroll 8
        for (int k = 0; k < HDIM; k++) a += P[gg][k] * fcW1[k * HDIM + n];
        Hm[gg][n] = (a >= 0.f) ? a : 0.01f * a;
    }
    __syncthreads();

    for (int idx = t; idx < GDIM * DDIM; idx += 256) {
        int gg = idx / DDIM, d = idx % DDIM;
        float a = fcb2[d];
#pragma unroll 8
        for (int k = 0; k < HDIM; k++) a += Hm[gg][k] * fcW2[k * DDIM + d];
        O[gg][d] = a;
    }
    __syncthreads();

    if (t < GDIM) {
        float s = 0.f;
#pragma unroll
        for (int d = 0; d < DDIM; d++) s += O[t][d] * O[t][d];
        float inv = 1.0f / fmaxf(sqrtf(s), 1e-12f);
        for (int d = 0; d < DDIM; d++) out[t * DDIM + d] = O[t][d] * inv;
    }
}

// ---------------- launch -----------------------------------------------------
extern "C" void kernel_launch(void* const* d_in, const int* in_sizes, int n_in,
                              void* d_out, int out_size) {
    const float* x    = (const float*)d_in[0];
    const int*   ei   = (const int*)d_in[1];
    const int*   batch= (const int*)d_in[2];
    const float* W1 = (const float*)d_in[3];
    const float* b1 = (const float*)d_in[4];
    const float* W2 = (const float*)d_in[5];
    const float* b2 = (const float*)d_in[6];
    const float* W3 = (const float*)d_in[7];
    const float* b3 = (const float*)d_in[8];
    const float* g1 = (const float*)d_in[9];
    const float* be1= (const float*)d_in[10];
    const float* m1 = (const float*)d_in[11];
    const float* v1 = (const float*)d_in[12];
    const float* g2 = (const float*)d_in[13];
    const float* be2= (const float*)d_in[14];
    const float* m2 = (const float*)d_in[15];
    const float* v2 = (const float*)d_in[16];
    const float* g3 = (const float*)d_in[17];
    const float* be3= (const float*)d_in[18];
    const float* m3 = (const float*)d_in[19];
    const float* v3 = (const float*)d_in[20];
    const float* fcW1 = (const float*)d_in[21];
    const float* fcb1 = (const float*)d_in[22];
    const float* fcW2 = (const float*)d_in[23];
    const float* fcb2 = (const float*)d_in[24];
    float* out = (float*)d_out;

    const int* srcp = ei;
    const int* dstp = ei + N_EDGES;

    float *bufA, *bufB;
    cudaGetSymbolAddress((void**)&bufA, g_bufA);
    cudaGetSymbolAddress((void**)&bufB, g_bufB);
    void *cntp, *poolp, *gcntp;
    cudaGetSymbolAddress(&cntp, g_cnt);
    cudaGetSymbolAddress(&poolp, g_pool);
    cudaGetSymbolAddress(&gcntp, g_gcnt);

    const int nscan = (N_NODES + 1023) / 1024;  // 98

    // --- CSR build (once per launch, shared by all 3 layers) ---
    cudaMemsetAsync(cntp, 0, N_NODES * sizeof(int));
    count_kernel<<<(N_EDGES + 255) / 256, 256>>>(dstp);
    scan_part_kernel<<<nscan, 1024>>>();
    scan_bsum_kernel<<<1, 128>>>(nscan);
    finalize_offs_kernel<<<(N_NODES + 255) / 256, 256>>>();
    fill_csr_kernel<<<(N_EDGES + 255) / 256, 256>>>(srcp, dstp);

    const int ngemm = (N_NODES + 127) / 128;
    const int nagg  = (N_NODES + 7) / 8;

    // layer 1: x -> bufA
    gemm_tf32_kernel<<<ngemm, 256>>>(x, W1);
    agg_post_kernel<<<nagg, 256>>>(b1, g1, be1, m1, v1, (const float*)0, bufA);
    // layer 2: bufA -> bufB (residual bufA)
    gemm_tf32_kernel<<<ngemm, 256>>>(bufA, W2);
    agg_post_kernel<<<nagg, 256>>>(b2, g2, be2, m2, v2, bufA, bufB);
    // layer 3: bufB -> bufA (residual bufB)
    gemm_tf32_kernel<<<ngemm, 256>>>(bufB, W3);
    agg_post_kernel<<<nagg, 256>>>(b3, g3, be3, m3, v3, bufB, bufA);

    // pooling + head
    cudaMemsetAsync(poolp, 0, GDIM * HDIM * sizeof(float));
    cudaMemsetAsync(gcntp, 0, GDIM * sizeof(float));
    pool_sum_kernel<<<(N_NODES + POOL_CHUNK - 1) / POOL_CHUNK, 128>>>(bufA, batch);
    head_kernel<<<1, 256>>>(fcW1, fcb1, fcW2, fcb2, out);
}

// round 4
// speedup vs baseline: 2.2099x; 1.2069x over previous
#include <cuda_runtime.h>
#include <cuda_fp16.h>
#include <mma.h>

using namespace nvcuda;

#define N_NODES 100000
#define N_EDGES 1600000
#define HDIM 128
#define GDIM 64
#define DDIM 64

// ---------------- scratch (device globals; no allocation allowed) ----------
__device__ __half g_hs[(size_t)N_NODES * HDIM];    // fp16 (A @ W) * dinv[row]
__device__ __half g_xh[(size_t)N_NODES * HDIM];    // fp16 copy of input x
__device__ __half g_bufA[(size_t)N_NODES * HDIM];  // x1 / x3 (fp16)
__device__ __half g_bufB[(size_t)N_NODES * HDIM];  // x2 (fp16)
__device__ __half g_Wh[3 * HDIM * HDIM];           // fp16 W1,W2,W3
__device__ int   g_cnt[N_NODES];
__device__ int   g_tmp[N_NODES];
__device__ int   g_offs[N_NODES + 1];
__device__ int   g_woff[N_NODES];
__device__ int   g_srcs[N_EDGES];
__device__ float g_dinv[N_NODES];
__device__ int   g_bsum[128];
__device__ float g_pool[GDIM * HDIM];
__device__ float g_gcnt[GDIM];

// ---------------- fp32 -> fp16 conversions ---------------------------------
__global__ void convert_x_kernel(const float* __restrict__ x) {
    int i = blockIdx.x * blockDim.x + threadIdx.x;  // float4 index
    if (i < N_NODES * HDIM / 4) {
        float4 v = ((const float4*)x)[i];
        __half2 h0 = __floats2half2_rn(v.x, v.y);
        __half2 h1 = __floats2half2_rn(v.z, v.w);
        uint2 u;
        u.x = *(const unsigned*)&h0;
        u.y = *(const unsigned*)&h1;
        ((uint2*)g_xh)[i] = u;
    }
}

__global__ void convert_w_kernel(const float* __restrict__ W1,
                                 const float* __restrict__ W2,
                                 const float* __restrict__ W3) {
    int i = blockIdx.x * blockDim.x + threadIdx.x;
    if (i < 3 * HDIM * HDIM) {
        int sel = i / (HDIM * HDIM);
        int off = i - sel * (HDIM * HDIM);
        const float* W = (sel == 0) ? W1 : (sel == 1) ? W2 : W3;
        g_Wh[i] = __float2half_rn(W[off]);
    }
}

// ---------------- CSR build ------------------------------------------------
__global__ void count_kernel(const int* __restrict__ dst) {
    int e = blockIdx.x * blockDim.x + threadIdx.x;
    if (e < N_EDGES) atomicAdd(&g_cnt[dst[e]], 1);
}

__global__ void scan_part_kernel() {
    __shared__ int s[1024];
    int i = blockIdx.x * 1024 + threadIdx.x;
    int v = (i < N_NODES) ? g_cnt[i] : 0;
    s[threadIdx.x] = v;
    __syncthreads();
#pragma unroll
    for (int off = 1; off < 1024; off <<= 1) {
        int t = 0;
        if (threadIdx.x >= off) t = s[threadIdx.x - off];
        __syncthreads();
        if (threadIdx.x >= off) s[threadIdx.x] += t;
        __syncthreads();
    }
    if (i < N_NODES) g_tmp[i] = s[threadIdx.x];
    if (threadIdx.x == 1023) g_bsum[blockIdx.x] = s[1023];
}

__global__ void scan_bsum_kernel(int nblocks) {
    __shared__ int s[128];
    int v = (threadIdx.x < nblocks) ? g_bsum[threadIdx.x] : 0;
    s[threadIdx.x] = v;
    __syncthreads();
#pragma unroll
    for (int off = 1; off < 128; off <<= 1) {
        int t = 0;
        if (threadIdx.x >= off) t = s[threadIdx.x - off];
        __syncthreads();
        if (threadIdx.x >= off) s[threadIdx.x] += t;
        __syncthreads();
    }
    g_bsum[threadIdx.x] = s[threadIdx.x] - v;  // exclusive
}

__global__ void finalize_offs_kernel() {
    int i = blockIdx.x * blockDim.x + threadIdx.x;
    if (i < N_NODES) {
        int bs = g_bsum[i >> 10];
        int incl = g_tmp[i] + bs;
        int excl = incl - g_cnt[i];
        g_offs[i] = excl;
        g_woff[i] = excl;
        g_dinv[i] = rsqrtf((float)g_cnt[i] + 1.0f);  // +1 self loop
        if (i == N_NODES - 1) g_offs[N_NODES] = incl;
    }
}

__global__ void fill_csr_kernel(const int* __restrict__ src, const int* __restrict__ dst) {
    int e = blockIdx.x * blockDim.x + threadIdx.x;
    if (e < N_EDGES) {
        int d = dst[e];
        int p = atomicAdd(&g_woff[d], 1);
        g_srcs[p] = src[e];
    }
}

// ---------------- GEMM (fp16 HMMA, fp32 accum): hs = fp16((A@W)*dinv[row]) -
// A: [N,128] fp16 row-major, W: [128,128] fp16 row-major.
// Block tile 128x128, 8 warps, warp tile 32x64 (2x4 wmma m16n16k16), BK=64.
#define GBK 64

__global__ __launch_bounds__(256) void gemm_f16_kernel(
    const __half* __restrict__ A, const __half* __restrict__ W) {
    __shared__ __half As[128][GBK + 8];    // 18432 B
    __shared__ __half Ws[GBK][HDIM + 8];   // 17408 B
    __shared__ float Cs[8][16][20];        // 10240 B epilogue staging

    int t = threadIdx.x;
    int warp = t >> 5;
    int lane = t & 31;
    int row0 = blockIdx.x * 128;
    int wm = warp >> 1;   // 0..3 -> rows wm*32
    int wn = warp & 1;    // 0..1 -> cols wn*64

    wmma::fragment<wmma::accumulator, 16, 16, 16, float> acc[2][4];
#pragma unroll
    for (int i = 0; i < 2; i++)
#pragma unroll
        for (int j = 0; j < 4; j++) wmma::fill_fragment(acc[i][j], 0.0f);

#pragma unroll
    for (int k0 = 0; k0 < HDIM; k0 += GBK) {
        // A tile: 128 rows x 64 halves (8 float4/row) = 1024 float4
#pragma unroll
        for (int i = 0; i < 4; i++) {
            int idx = t + i * 256;
            int r = idx >> 3;
            int c = (idx & 7) * 8;  // halves
            int grow = row0 + r;
            float4 v = make_float4(0.f, 0.f, 0.f, 0.f);
            if (grow < N_NODES)
                v = *(const float4*)&A[(size_t)grow * HDIM + k0 + c];
            *(float4*)&As[r][c] = v;
        }
        // W tile: 64 rows x 128 halves (16 float4/row) = 1024 float4
#pragma unroll
        for (int i = 0; i < 4; i++) {
            int idx = t + i * 256;
            int r = idx >> 4;
            int c = (idx & 15) * 8;
            *(float4*)&Ws[r][c] = *(const float4*)&W[(size_t)(k0 + r) * HDIM + c];
        }
        __syncthreads();

#pragma unroll
        for (int kk = 0; kk < GBK; kk += 16) {
            wmma::fragment<wmma::matrix_a, 16, 16, 16, __half, wmma::row_major> af[2];
#pragma unroll
            for (int i = 0; i < 2; i++)
                wmma::load_matrix_sync(af[i], &As[wm * 32 + i * 16][kk], GBK + 8);
            wmma::fragment<wmma::matrix_b, 16, 16, 16, __half, wmma::row_major> bf[4];
#pragma unroll
            for (int j = 0; j < 4; j++)
                wmma::load_matrix_sync(bf[j], &Ws[kk][wn * 64 + j * 16], HDIM + 8);
#pragma unroll
            for (int i = 0; i < 2; i++)
#pragma unroll
                for (int j = 0; j < 4; j++)
                    wmma::mma_sync(acc[i][j], af[i], bf[j], acc[i][j]);
        }
        __syncthreads();
    }

    // epilogue: stage 16x16 tiles via smem, scale by dinv[row], fp16 store
#pragma unroll
    for (int i = 0; i < 2; i++) {
#pragma unroll
        for (int j = 0; j < 4; j++) {
            wmma::store_matrix_sync(&Cs[warp][0][0], acc[i][j], 20,
                                    wmma::mem_row_major);
            __syncwarp();
#pragma unroll
            for (int it = 0; it < 2; it++) {
                int f4 = lane + it * 32;     // 0..63
                int r = f4 >> 2;             // 0..15
                int c4 = f4 & 3;             // 0..3
                int grow = row0 + wm * 32 + i * 16 + r;
                if (grow < N_NODES) {
                    float dv = g_dinv[grow];
                    float4 v = *(float4*)&Cs[warp][r][c4 * 4];
                    __half2 h0 = __floats2half2_rn(v.x * dv, v.y * dv);
                    __half2 h1 = __floats2half2_rn(v.z * dv, v.w * dv);
                    uint2 u;
                    u.x = *(const unsigned*)&h0;
                    u.y = *(const unsigned*)&h1;
                    *(uint2*)&g_hs[(size_t)grow * HDIM + wn * 64 + j * 16 + c4 * 4] = u;
                }
            }
            __syncwarp();
        }
    }
}

// ---------------- aggregation + bias + BN + LeakyReLU + residual -----------
// One warp per node; lane handles 4 features. fp32 accum, fp16 in/out.
__global__ __launch_bounds__(256) void agg_post_kernel(
    const float* __restrict__ b, const float* __restrict__ g,
    const float* __restrict__ be, const float* __restrict__ m,
    const float* __restrict__ v, const __half* __restrict__ res,
    __half* __restrict__ out) {
    int node = blockIdx.x * 8 + (threadIdx.x >> 5);
    int lane = threadIdx.x & 31;
    if (node >= N_NODES) return;

    const uint2* hsu = (const uint2*)g_hs;  // row stride = 32 uint2

    uint2 u0 = hsu[(size_t)node * 32 + lane];
    float2 f0 = __half22float2(*(const __half2*)&u0.x);
    float2 f1 = __half22float2(*(const __half2*)&u0.y);
    float sx = f0.x, sy = f0.y, sz = f1.x, sw = f1.y;

    int e0 = g_offs[node], e1 = g_offs[node + 1];
    int e = e0;
    for (; e + 4 <= e1; e += 4) {
        int s0 = g_srcs[e], s1 = g_srcs[e + 1], s2 = g_srcs[e + 2], s3 = g_srcs[e + 3];
        uint2 a0 = hsu[(size_t)s0 * 32 + lane];
        uint2 a1 = hsu[(size_t)s1 * 32 + lane];
        uint2 a2 = hsu[(size_t)s2 * 32 + lane];
        uint2 a3 = hsu[(size_t)s3 * 32 + lane];
        float2 p;
        p = __half22float2(*(const __half2*)&a0.x); sx += p.x; sy += p.y;
        p = __half22float2(*(const __half2*)&a0.y); sz += p.x; sw += p.y;
        p = __half22float2(*(const __half2*)&a1.x); sx += p.x; sy += p.y;
        p = __half22float2(*(const __half2*)&a1.y); sz += p.x; sw += p.y;
        p = __half22float2(*(const __half2*)&a2.x); sx += p.x; sy += p.y;
        p = __half22float2(*(const __half2*)&a2.y); sz += p.x; sw += p.y;
        p = __half22float2(*(const __half2*)&a3.x); sx += p.x; sy += p.y;
        p = __half22float2(*(const __half2*)&a3.y); sz += p.x; sw += p.y;
    }
    for (; e < e1; e++) {
        uint2 a0 = hsu[(size_t)g_srcs[e] * 32 + lane];
        float2 p;
        p = __half22float2(*(const __half2*)&a0.x); sx += p.x; sy += p.y;
        p = __half22float2(*(const __half2*)&a0.y); sz += p.x; sw += p.y;
    }

    int c = lane * 4;
    float dv = g_dinv[node];
    float4 bb = *(const float4*)&b[c];
    float4 gg = *(const float4*)&g[c];
    float4 bee = *(const float4*)&be[c];
    float4 mm = *(const float4*)&m[c];
    float4 vv = *(const float4*)&v[c];

    float4 r4;
    r4.x = (sx * dv + bb.x - mm.x) * rsqrtf(vv.x + 1e-5f) * gg.x + bee.x;
    r4.y = (sy * dv + bb.y - mm.y) * rsqrtf(vv.y + 1e-5f) * gg.y + bee.y;
    r4.z = (sz * dv + bb.z - mm.z) * rsqrtf(vv.z + 1e-5f) * gg.z + bee.z;
    r4.w = (sw * dv + bb.w - mm.w) * rsqrtf(vv.w + 1e-5f) * gg.w + bee.w;
    r4.x = (r4.x >= 0.f) ? r4.x : 0.01f * r4.x;
    r4.y = (r4.y >= 0.f) ? r4.y : 0.01f * r4.y;
    r4.z = (r4.z >= 0.f) ? r4.z : 0.01f * r4.z;
    r4.w = (r4.w >= 0.f) ? r4.w : 0.01f * r4.w;

    if (res) {
        uint2 ru = *(const uint2*)&res[(size_t)node * HDIM + c];
        float2 p0 = __half22float2(*(const __half2*)&ru.x);
        float2 p1 = __half22float2(*(const __half2*)&ru.y);
        r4.x += p0.x; r4.y += p0.y; r4.z += p1.x; r4.w += p1.y;
    }
    __half2 h0 = __floats2half2_rn(r4.x, r4.y);
    __half2 h1 = __floats2half2_rn(r4.z, r4.w);
    uint2 u;
    u.x = *(const unsigned*)&h0;
    u.y = *(const unsigned*)&h1;
    *(uint2*)&out[(size_t)node * HDIM + c] = u;
}

// ---------------- pooling ---------------------------------------------------
#define POOL_CHUNK 256
__global__ void pool_sum_kernel(const __half* __restrict__ x,
                                const int* __restrict__ batch) {
    int f = threadIdx.x;  // 128
    int n0 = blockIdx.x * POOL_CHUNK;
    int n1 = n0 + POOL_CHUNK;
    if (n1 > N_NODES) n1 = N_NODES;
    if (n0 >= N_NODES) return;

    float acc = 0.f;
    int cur = batch[n0];
    int cnt = 0;
    for (int i = n0; i < n1; i++) {
        int gid = batch[i];
        if (gid != cur) {
            atomicAdd(&g_pool[cur * HDIM + f], acc);
            if (f == 0) atomicAdd(&g_gcnt[cur], (float)cnt);
            acc = 0.f;
            cnt = 0;
            cur = gid;
        }
        acc += __half2float(x[(size_t)i * HDIM + f]);
        cnt++;
    }
    atomicAdd(&g_pool[cur * HDIM + f], acc);
    if (f == 0) atomicAdd(&g_gcnt[cur], (float)cnt);
}

// ---------------- MLP head + mean + L2-normalize (single block) ------------
__global__ __launch_bounds__(256) void head_kernel(
    const float* __restrict__ fcW1, const float* __restrict__ fcb1,
    const float* __restrict__ fcW2, const float* __restrict__ fcb2,
    float* __restrict__ out) {
    __shared__ float P[GDIM][HDIM];   // mean-pooled
    __shared__ float Hm[GDIM][HDIM];
    __shared__ float O[GDIM][DDIM];
    __shared__ float invc[GDIM];
    int t = threadIdx.x;

    if (t < GDIM) invc[t] = 1.0f / fmaxf(g_gcnt[t], 1.0f);
    __syncthreads();
    for (int idx = t; idx < GDIM * HDIM; idx += 256)
        P[idx / HDIM][idx % HDIM] = g_pool[idx] * invc[idx / HDIM];
    __syncthreads();

    for (int idx = t; idx < GDIM * HDIM; idx += 256) {
        int gg = idx / HDIM, n = idx % HDIM;
        float a = fcb1[n];
#pragma unroll 8
        for (int k = 0; k < HDIM; k++) a += P[gg][k] * fcW1[k * HDIM + n];
        Hm[gg][n] = (a >= 0.f) ? a : 0.01f * a;
    }
    __syncthreads();

    for (int idx = t; idx < GDIM * DDIM; idx += 256) {
        int gg = idx / DDIM, d = idx % DDIM;
        float a = fcb2[d];
#pragma unroll 8
        for (int k = 0; k < HDIM; k++) a += Hm[gg][k] * fcW2[k * DDIM + d];
        O[gg][d] = a;
    }
    __syncthreads();

    if (t < GDIM) {
        float s = 0.f;
#pragma unroll
        for (int d = 0; d < DDIM; d++) s += O[t][d] * O[t][d];
        float inv = 1.0f / fmaxf(sqrtf(s), 1e-12f);
        for (int d = 0; d < DDIM; d++) out[t * DDIM + d] = O[t][d] * inv;
    }
}

// ---------------- launch -----------------------------------------------------
extern "C" void kernel_launch(void* const* d_in, const int* in_sizes, int n_in,
                              void* d_out, int out_size) {
    const float* x    = (const float*)d_in[0];
    const int*   ei   = (const int*)d_in[1];
    const int*   batch= (const int*)d_in[2];
    const float* W1 = (const float*)d_in[3];
    const float* b1 = (const float*)d_in[4];
    const float* W2 = (const float*)d_in[5];
    const float* b2 = (const float*)d_in[6];
    const float* W3 = (const float*)d_in[7];
    const float* b3 = (const float*)d_in[8];
    const float* g1 = (const float*)d_in[9];
    const float* be1= (const float*)d_in[10];
    const float* m1 = (const float*)d_in[11];
    const float* v1 = (const float*)d_in[12];
    const float* g2 = (const float*)d_in[13];
    const float* be2= (const float*)d_in[14];
    const float* m2 = (const float*)d_in[15];
    const float* v2 = (const float*)d_in[16];
    const float* g3 = (const float*)d_in[17];
    const float* be3= (const float*)d_in[18];
    const float* m3 = (const float*)d_in[19];
    const float* v3 = (const float*)d_in[20];
    const float* fcW1 = (const float*)d_in[21];
    const float* fcb1 = (const float*)d_in[22];
    const float* fcW2 = (const float*)d_in[23];
    const float* fcb2 = (const float*)d_in[24];
    float* out = (float*)d_out;

    const int* srcp = ei;
    const int* dstp = ei + N_EDGES;

    __half *xh, *bufA, *bufB, *Wh;
    cudaGetSymbolAddress((void**)&xh, g_xh);
    cudaGetSymbolAddress((void**)&bufA, g_bufA);
    cudaGetSymbolAddress((void**)&bufB, g_bufB);
    cudaGetSymbolAddress((void**)&Wh, g_Wh);
    void *cntp, *poolp, *gcntp;
    cudaGetSymbolAddress(&cntp, g_cnt);
    cudaGetSymbolAddress(&poolp, g_pool);
    cudaGetSymbolAddress(&gcntp, g_gcnt);

    const int nscan = (N_NODES + 1023) / 1024;  // 98

    // --- conversions + CSR build ---
    cudaMemsetAsync(cntp, 0, N_NODES * sizeof(int));
    convert_x_kernel<<<(N_NODES * HDIM / 4 + 255) / 256, 256>>>(x);
    convert_w_kernel<<<(3 * HDIM * HDIM + 255) / 256, 256>>>(W1, W2, W3);
    count_kernel<<<(N_EDGES + 255) / 256, 256>>>(dstp);
    scan_part_kernel<<<nscan, 1024>>>();
    scan_bsum_kernel<<<1, 128>>>(nscan);
    finalize_offs_kernel<<<(N_NODES + 255) / 256, 256>>>();
    fill_csr_kernel<<<(N_EDGES + 255) / 256, 256>>>(srcp, dstp);

    const int ngemm = (N_NODES + 127) / 128;
    const int nagg  = (N_NODES + 7) / 8;

    // layer 1: xh -> bufA
    gemm_f16_kernel<<<ngemm, 256>>>(xh, Wh);
    agg_post_kernel<<<nagg, 256>>>(b1, g1, be1, m1, v1, (const __half*)0, bufA);
    // layer 2: bufA -> bufB (residual bufA)
    gemm_f16_kernel<<<ngemm, 256>>>(bufA, Wh + HDIM * HDIM);
    agg_post_kernel<<<nagg, 256>>>(b2, g2, be2, m2, v2, bufA, bufB);
    // layer 3: bufB -> bufA (residual bufB)
    gemm_f16_kernel<<<ngemm, 256>>>(bufB, Wh + 2 * HDIM * HDIM);
    agg_post_kernel<<<nagg, 256>>>(b3, g3, be3, m3, v3, bufB, bufA);

    // pooling + head
    cudaMemsetAsync(poolp, 0, GDIM * HDIM * sizeof(float));
    cudaMemsetAsync(gcntp, 0, GDIM * sizeof(float));
    pool_sum_kernel<<<(N_NODES + POOL_CHUNK - 1) / POOL_CHUNK, 128>>>(bufA, batch);
    head_kernel<<<1, 256>>>(fcW1, fcb1, fcW2, fcb2, out);
}